// round 2
// baseline (speedup 1.0000x reference)
#include <cuda_runtime.h>

#define BB 4
#define LL 2048
#define DD 1024
#define NH 16
#define HDIM 64
#define QKVN (NH * HDIM * 3)   // 3072
#define NROWS (BB * LL)        // 8192

// ---- scratch (static device globals; no dynamic allocation) ----
__device__ float g_qkv[(size_t)NROWS * QKVN];          // 96 MB
__device__ float g_newv[(size_t)NROWS * (NH * HDIM)];  // 32 MB
__device__ float g_hbuf[(size_t)NROWS * DD];           // 32 MB

__device__ __forceinline__ float swish_f(float v) {
    return v * (1.0f / (1.0f + __expf(-v)));
}

// ============================================================================
// SGEMM 128x128x8, 256 threads, 8x8 per thread.
// EPI=0: C = swish(A*B + bias)
// EPI=1: C = skip + swish(A*B + bias)
// ============================================================================
template <int EPI>
__global__ void __launch_bounds__(256, 2)
sgemm_kernel(const float* __restrict__ A, const float* __restrict__ Bm,
             const float* __restrict__ bias, const float* __restrict__ skip,
             float* __restrict__ C, int M, int N, int K)
{
    __shared__ float As[8][128];   // As[k][m]
    __shared__ float Bs[8][128];   // Bs[k][n]

    const int tid = threadIdx.x;
    const int bm = blockIdx.y, bn = blockIdx.x;
    const int arow = tid >> 1;            // 0..127
    const int acol = (tid & 1) << 2;      // 0 or 4
    const int brow = tid >> 5;            // 0..7
    const int bcol = (tid & 31) << 2;     // 0..124
    const int ty = tid >> 4, tx = tid & 15;

    const float* Ap = A + (size_t)(bm * 128 + arow) * K + acol;
    const float* Bp = Bm + (size_t)brow * N + bn * 128 + bcol;

    float acc[8][8] = {};

    for (int k0 = 0; k0 < K; k0 += 8) {
        float4 av = *(const float4*)(Ap + k0);
        float4 bv = *(const float4*)(Bp + (size_t)k0 * N);
        As[acol + 0][arow] = av.x;
        As[acol + 1][arow] = av.y;
        As[acol + 2][arow] = av.z;
        As[acol + 3][arow] = av.w;
        *(float4*)(&Bs[brow][bcol]) = bv;
        __syncthreads();

        #pragma unroll
        for (int kk = 0; kk < 8; kk++) {
            float ar[8], br[8];
            *(float4*)&ar[0] = *(const float4*)&As[kk][ty * 8];
            *(float4*)&ar[4] = *(const float4*)&As[kk][ty * 8 + 4];
            *(float4*)&br[0] = *(const float4*)&Bs[kk][tx * 8];
            *(float4*)&br[4] = *(const float4*)&Bs[kk][tx * 8 + 4];
            #pragma unroll
            for (int i = 0; i < 8; i++)
                #pragma unroll
                for (int j = 0; j < 8; j++)
                    acc[i][j] = fmaf(ar[i], br[j], acc[i][j]);
        }
        __syncthreads();
    }

    // epilogue
    #pragma unroll
    for (int i = 0; i < 8; i++) {
        const size_t row = (size_t)bm * 128 + ty * 8 + i;
        #pragma unroll
        for (int j = 0; j < 8; j += 4) {
            const int col = bn * 128 + tx * 8 + j;
            float vv[4];
            #pragma unroll
            for (int jj = 0; jj < 4; jj++) {
                float v = acc[i][j + jj] + bias[col + jj];
                float sw = swish_f(v);
                if (EPI == 1) sw += skip[row * (size_t)N + col + jj];
                vv[jj] = sw;
            }
            *(float4*)&C[row * (size_t)N + col] =
                make_float4(vv[0], vv[1], vv[2], vv[3]);
        }
    }
}

// ============================================================================
// Flash attention, fp32. One block = (b, h, 64-query tile). 256 threads.
// Q,K stored transposed in smem (d-major, pad 65). S tile in smem (pad 65).
// Online softmax with running max/sum. scale = 1/sqrt(L) folded into Q.
// ============================================================================
#define SM_QST 0
#define SM_KST 4160
#define SM_VS  8320
#define SM_SS  12416
#define SM_M   16576
#define SM_L   16640
#define SM_A   16704
#define SM_FLOATS 16768   // 67072 bytes

__global__ void __launch_bounds__(256, 2)
attn_kernel(const float* __restrict__ qkv, float* __restrict__ nv)
{
    extern __shared__ float sm[];
    float* Qst = sm + SM_QST;   // [64][65], Qst[d*65 + r]
    float* Kst = sm + SM_KST;   // [64][65], Kst[d*65 + c]
    float* Vs  = sm + SM_VS;    // [64][64], Vs[k*64 + d]
    float* Ss  = sm + SM_SS;    // [64][65], Ss[r*65 + c]
    float* m_s = sm + SM_M;
    float* l_s = sm + SM_L;
    float* a_s = sm + SM_A;

    const int qt = blockIdx.x, h = blockIdx.y, b = blockIdx.z;
    const int tid = threadIdx.x;
    const int ty = tid >> 4, tx = tid & 15;
    const int wid = tid >> 5, lane = tid & 31;
    const float scale = 0.022097086912079608f;  // 1/sqrt(2048)
    const size_t rowbase = (size_t)b * LL;
    const int hoff = h * (3 * HDIM);

    // load Q tile (transposed + scaled)
    #pragma unroll
    for (int it = 0; it < 4; it++) {
        int fid = it * 256 + tid;
        int r = fid >> 4;
        int c4 = (fid & 15) << 2;
        const float* p = qkv + (rowbase + qt * 64 + r) * QKVN + hoff + c4;
        float4 v = *(const float4*)p;
        Qst[(c4 + 0) * 65 + r] = v.x * scale;
        Qst[(c4 + 1) * 65 + r] = v.y * scale;
        Qst[(c4 + 2) * 65 + r] = v.z * scale;
        Qst[(c4 + 3) * 65 + r] = v.w * scale;
    }
    if (tid < 64) { m_s[tid] = -3.0e38f; l_s[tid] = 0.0f; }

    float o[4][4] = {};

    for (int kt = 0; kt < LL / 64; kt++) {
        // load K (transposed) and V tiles
        #pragma unroll
        for (int it = 0; it < 4; it++) {
            int fid = it * 256 + tid;
            int r = fid >> 4;
            int c4 = (fid & 15) << 2;
            const float* pk = qkv + (rowbase + kt * 64 + r) * QKVN + hoff + HDIM + c4;
            float4 kv = *(const float4*)pk;
            Kst[(c4 + 0) * 65 + r] = kv.x;
            Kst[(c4 + 1) * 65 + r] = kv.y;
            Kst[(c4 + 2) * 65 + r] = kv.z;
            Kst[(c4 + 3) * 65 + r] = kv.w;
            const float* pv = qkv + (rowbase + kt * 64 + r) * QKVN + hoff + 2 * HDIM + c4;
            *(float4*)&Vs[r * 64 + c4] = *(const float4*)pv;
        }
        __syncthreads();

        // S = Q K^T (64x64, each thread 4x4)
        float s[4][4] = {};
        #pragma unroll 8
        for (int k = 0; k < 64; k++) {
            float a0 = Qst[k * 65 + ty * 4 + 0];
            float a1 = Qst[k * 65 + ty * 4 + 1];
            float a2 = Qst[k * 65 + ty * 4 + 2];
            float a3 = Qst[k * 65 + ty * 4 + 3];
            float b0 = Kst[k * 65 + tx * 4 + 0];
            float b1 = Kst[k * 65 + tx * 4 + 1];
            float b2 = Kst[k * 65 + tx * 4 + 2];
            float b3 = Kst[k * 65 + tx * 4 + 3];
            s[0][0] = fmaf(a0, b0, s[0][0]); s[0][1] = fmaf(a0, b1, s[0][1]);
            s[0][2] = fmaf(a0, b2, s[0][2]); s[0][3] = fmaf(a0, b3, s[0][3]);
            s[1][0] = fmaf(a1, b0, s[1][0]); s[1][1] = fmaf(a1, b1, s[1][1]);
            s[1][2] = fmaf(a1, b2, s[1][2]); s[1][3] = fmaf(a1, b3, s[1][3]);
            s[2][0] = fmaf(a2, b0, s[2][0]); s[2][1] = fmaf(a2, b1, s[2][1]);
            s[2][2] = fmaf(a2, b2, s[2][2]); s[2][3] = fmaf(a2, b3, s[2][3]);
            s[3][0] = fmaf(a3, b0, s[3][0]); s[3][1] = fmaf(a3, b1, s[3][1]);
            s[3][2] = fmaf(a3, b2, s[3][2]); s[3][3] = fmaf(a3, b3, s[3][3]);
        }
        #pragma unroll
        for (int i = 0; i < 4; i++)
            #pragma unroll
            for (int j = 0; j < 4; j++)
                Ss[(ty * 4 + i) * 65 + tx * 4 + j] = s[i][j];
        __syncthreads();

        // online softmax: warp wid owns rows [wid*8, wid*8+8)
        #pragma unroll
        for (int rr = 0; rr < 8; rr++) {
            int row = wid * 8 + rr;
            float v0 = Ss[row * 65 + lane];
            float v1 = Ss[row * 65 + 32 + lane];
            float mx = fmaxf(v0, v1);
            #pragma unroll
            for (int off = 16; off > 0; off >>= 1)
                mx = fmaxf(mx, __shfl_xor_sync(0xffffffffu, mx, off));
            float mprev = m_s[row];
            float mnew = fmaxf(mprev, mx);
            float p0 = __expf(v0 - mnew);
            float p1 = __expf(v1 - mnew);
            Ss[row * 65 + lane] = p0;
            Ss[row * 65 + 32 + lane] = p1;
            float sum = p0 + p1;
            #pragma unroll
            for (int off = 16; off > 0; off >>= 1)
                sum += __shfl_xor_sync(0xffffffffu, sum, off);
            if (lane == 0) {
                float alpha = __expf(mprev - mnew);
                l_s[row] = l_s[row] * alpha + sum;
                m_s[row] = mnew;
                a_s[row] = alpha;
            }
        }
        __syncthreads();

        // rescale O, accumulate O += P V
        {
            float al0 = a_s[ty * 4 + 0], al1 = a_s[ty * 4 + 1];
            float al2 = a_s[ty * 4 + 2], al3 = a_s[ty * 4 + 3];
            #pragma unroll
            for (int j = 0; j < 4; j++) {
                o[0][j] *= al0; o[1][j] *= al1; o[2][j] *= al2; o[3][j] *= al3;
            }
        }
        #pragma unroll 8
        for (int k = 0; k < 64; k++) {
            float a0 = Ss[(ty * 4 + 0) * 65 + k];
            float a1 = Ss[(ty * 4 + 1) * 65 + k];
            float a2 = Ss[(ty * 4 + 2) * 65 + k];
            float a3 = Ss[(ty * 4 + 3) * 65 + k];
            float4 bv = *(const float4*)&Vs[k * 64 + tx * 4];
            o[0][0] = fmaf(a0, bv.x, o[0][0]); o[0][1] = fmaf(a0, bv.y, o[0][1]);
            o[0][2] = fmaf(a0, bv.z, o[0][2]); o[0][3] = fmaf(a0, bv.w, o[0][3]);
            o[1][0] = fmaf(a1, bv.x, o[1][0]); o[1][1] = fmaf(a1, bv.y, o[1][1]);
            o[1][2] = fmaf(a1, bv.z, o[1][2]); o[1][3] = fmaf(a1, bv.w, o[1][3]);
            o[2][0] = fmaf(a2, bv.x, o[2][0]); o[2][1] = fmaf(a2, bv.y, o[2][1]);
            o[2][2] = fmaf(a2, bv.z, o[2][2]); o[2][3] = fmaf(a2, bv.w, o[2][3]);
            o[3][0] = fmaf(a3, bv.x, o[3][0]); o[3][1] = fmaf(a3, bv.y, o[3][1]);
            o[3][2] = fmaf(a3, bv.z, o[3][2]); o[3][3] = fmaf(a3, bv.w, o[3][3]);
        }
        __syncthreads();
    }

    // final normalize + write
    #pragma unroll
    for (int i = 0; i < 4; i++) {
        const size_t row = rowbase + qt * 64 + ty * 4 + i;
        const float li = 1.0f / l_s[ty * 4 + i];
        float4 ov = make_float4(o[i][0] * li, o[i][1] * li, o[i][2] * li, o[i][3] * li);
        *(float4*)&nv[row * (size_t)(NH * HDIM) + h * HDIM + tx * 4] = ov;
    }
}

// ============================================================================
// LayerNorm over D=1024. One block (256 threads) per row, 1 float4/thread.
// ============================================================================
__global__ void __launch_bounds__(256)
ln_kernel(const float* __restrict__ hb, float* __restrict__ out)
{
    const int row = blockIdx.x;
    const float4* p4 = (const float4*)(hb + (size_t)row * DD);
    float4 v = p4[threadIdx.x];
    float s  = v.x + v.y + v.z + v.w;
    float s2 = v.x * v.x + v.y * v.y + v.z * v.z + v.w * v.w;

    __shared__ float rs[8], rs2[8];
    const int wid = threadIdx.x >> 5, lane = threadIdx.x & 31;
    #pragma unroll
    for (int off = 16; off > 0; off >>= 1) {
        s  += __shfl_xor_sync(0xffffffffu, s, off);
        s2 += __shfl_xor_sync(0xffffffffu, s2, off);
    }
    if (lane == 0) { rs[wid] = s; rs2[wid] = s2; }
    __syncthreads();
    if (threadIdx.x == 0) {
        float a = 0.f, b2 = 0.f;
        #pragma unroll
        for (int i = 0; i < 8; i++) { a += rs[i]; b2 += rs2[i]; }
        rs[0] = a; rs2[0] = b2;
    }
    __syncthreads();
    const float mu = rs[0] * (1.0f / DD);
    const float var = rs2[0] * (1.0f / DD) - mu * mu;
    const float rstd = rsqrtf(var + 1e-5f);
    float4 ov = make_float4((v.x - mu) * rstd, (v.y - mu) * rstd,
                            (v.z - mu) * rstd, (v.w - mu) * rstd);
    ((float4*)(out + (size_t)row * DD))[threadIdx.x] = ov;
}

// ============================================================================
extern "C" void kernel_launch(void* const* d_in, const int* in_sizes, int n_in,
                              void* d_out, int out_size)
{
    const float* x     = (const float*)d_in[0];
    const float* W_fc  = (const float*)d_in[1];
    const float* b_fc  = (const float*)d_in[2];
    const float* W_fc2 = (const float*)d_in[3];
    const float* b_fc2 = (const float*)d_in[4];
    float* out = (float*)d_out;

    void* p;
    cudaGetSymbolAddress(&p, g_qkv);  float* qkv = (float*)p;
    cudaGetSymbolAddress(&p, g_newv); float* nv  = (float*)p;
    cudaGetSymbolAddress(&p, g_hbuf); float* hb  = (float*)p;

    // GEMM1: qkv = swish(x @ W_fc + b_fc)   [8192,1024]x[1024,3072]
    dim3 g1(QKVN / 128, NROWS / 128);
    sgemm_kernel<0><<<g1, 256>>>(x, W_fc, b_fc, nullptr, qkv, NROWS, QKVN, DD);

    // Attention: nv = softmax(q k^T / sqrt(L)) v
    const int smem_bytes = SM_FLOATS * 4;
    cudaFuncSetAttribute(attn_kernel,
                         cudaFuncAttributeMaxDynamicSharedMemorySize, smem_bytes);
    dim3 ga(LL / 64, NH, BB);
    attn_kernel<<<ga, 256, smem_bytes>>>(qkv, nv);

    // GEMM2: hb = x + swish(nv @ W_fc2 + b_fc2)
    dim3 g2(DD / 128, NROWS / 128);
    sgemm_kernel<1><<<g2, 256>>>(nv, W_fc2, b_fc2, x, hb, NROWS, DD, DD);

    // LayerNorm -> out
    ln_kernel<<<NROWS, 256>>>(hb, out);
}